// round 5
// baseline (speedup 1.0000x reference)
#include <cuda_runtime.h>
#include <mma.h>
#include <cfloat>
#include <cstdint>

using namespace nvcuda;

#define L_  8
#define D_  1024
#define H_  16
#define T_  1024
#define V_  2048
#define B_  8
#define DH_ 64
#define FF_ 4096
#define M_  (B_ * T_)   // 8192 rows

// ---------------- scratch (device globals; no allocation allowed) -------------
__device__ float g_x [ (size_t)M_ * D_ ];
__device__ float g_h [ (size_t)M_ * D_ ];
__device__ float g_q [ (size_t)M_ * D_ ];
__device__ float g_k [ (size_t)M_ * D_ ];
__device__ float g_v [ (size_t)M_ * D_ ];
__device__ float g_o [ (size_t)M_ * D_ ];
__device__ float g_ff[ (size_t)M_ * FF_ ];
__device__ float g_s [ (size_t)B_ * H_ * T_ * T_ ];   // 512 MB attention scores

// ---------------- helpers ----------------------------------------------------
__device__ __forceinline__ float gelu_f(float x) {
    return 0.5f * x * (1.0f + erff(x * 0.70710678118654752f));
}

// =============================================================================
// Generic tiled GEMM, tf32 WMMA with 3-term fp32-emulation split.
//   C = A(MxK) * B(KxN) [+ bias] [+ gelu | + residual]
//   BT=true  : B is accessed transposed (B[k,n] = Bm[n*ldb + k])  (for Q K^T)
//   Batched via blockIdx.z with two-level (outer/inner) strides:
//       off = (z / innerDiv) * sOuter + (z % innerDiv) * sInner
// Assumes: M%BM==0, N%BN==0, K%BK==0 (true for every call here), 256 threads.
// =============================================================================
template<int BM, int BN, int BK, int WM, int WN, bool BT, int EPI>
__global__ __launch_bounds__(256)
void gemm_kernel(const float* __restrict__ A, const float* __restrict__ Bm,
                 const float* __restrict__ bias, const float* __restrict__ res,
                 float* __restrict__ C,
                 int M, int N, int K, int lda, int ldb, int ldc,
                 int innerDiv,
                 long long aOut, long long aIn,
                 long long bOut, long long bIn,
                 long long cOut, long long cIn)
{
    constexpr int MW    = BM / WM;        // warps along M
    constexpr int NW    = BN / WN;        // warps along N
    constexpr int NWARP = MW * NW;
    static_assert(NWARP == 8, "expect 256 threads");
    constexpr int LDA_S = BK + 4;
    constexpr int LDB_S = BN + 4;
    constexpr int LDS_T = WN + 4;
    constexpr int MI = WM / 16;
    constexpr int NI = WN / 16;

    __shared__ float sm[BM * LDA_S + BK * LDB_S];
    float* As = sm;
    float* Bs = sm + BM * LDA_S;

    const int z = blockIdx.z;
    const long long offA = (long long)(z / innerDiv) * aOut + (long long)(z % innerDiv) * aIn;
    const long long offB = (long long)(z / innerDiv) * bOut + (long long)(z % innerDiv) * bIn;
    const long long offC = (long long)(z / innerDiv) * cOut + (long long)(z % innerDiv) * cIn;
    A  += offA;
    Bm += offB;
    C  += offC;
    if constexpr (EPI == 2) res += offC;

    const int bm   = blockIdx.y * BM;
    const int bn   = blockIdx.x * BN;
    const int tid  = threadIdx.x;
    const int warp = tid >> 5;
    const int lane = tid & 31;
    const int wm   = (warp % MW) * WM;
    const int wn   = (warp / MW) * WN;

    wmma::fragment<wmma::accumulator, 16, 16, 8, float> acc[MI][NI];
    #pragma unroll
    for (int i = 0; i < MI; i++)
        #pragma unroll
        for (int j = 0; j < NI; j++)
            wmma::fill_fragment(acc[i][j], 0.0f);

    for (int k0 = 0; k0 < K; k0 += BK) {
        // ---- load A tile (BM x BK), row-major, float4 ----
        #pragma unroll
        for (int p = 0; p < BM / 32; ++p) {
            int r = p * 32 + (tid >> 3);
            int c = (tid & 7) * 4;
            float4 t4 = *reinterpret_cast<const float4*>(A + (long long)(bm + r) * lda + k0 + c);
            *reinterpret_cast<float4*>(&As[r * LDA_S + c]) = t4;
        }
        // ---- load B tile (BK x BN) ----
        if constexpr (!BT) {
            constexpr int F4R = BN / 4;          // float4 per row
            constexpr int RPP = 256 / F4R;       // rows per pass
            #pragma unroll
            for (int p = 0; p < BK / RPP; ++p) {
                int r = p * RPP + tid / F4R;
                int c = (tid % F4R) * 4;
                float4 t4 = *reinterpret_cast<const float4*>(Bm + (long long)(k0 + r) * ldb + bn + c);
                *reinterpret_cast<float4*>(&Bs[r * LDB_S + c]) = t4;
            }
        } else {
            // Bs[k][n] = Bm[(bn+n)*ldb + k0+k]  (transpose in-flight)
            constexpr int F4C = BK / 4;          // float4 along k per column
            constexpr int CPP = 256 / F4C;       // columns per pass
            #pragma unroll
            for (int p = 0; p < BN / CPP; ++p) {
                int n  = p * CPP + tid / F4C;
                int kk = (tid % F4C) * 4;
                float4 t4 = *reinterpret_cast<const float4*>(Bm + (long long)(bn + n) * ldb + k0 + kk);
                Bs[(kk + 0) * LDB_S + n] = t4.x;
                Bs[(kk + 1) * LDB_S + n] = t4.y;
                Bs[(kk + 2) * LDB_S + n] = t4.z;
                Bs[(kk + 3) * LDB_S + n] = t4.w;
            }
        }
        __syncthreads();

        #pragma unroll
        for (int kk = 0; kk < BK; kk += 8) {
            wmma::fragment<wmma::matrix_a, 16, 16, 8, wmma::precision::tf32, wmma::row_major> ahi[MI], alo[MI];
            wmma::fragment<wmma::matrix_b, 16, 16, 8, wmma::precision::tf32, wmma::row_major> bhi[NI], blo[NI];
            #pragma unroll
            for (int i = 0; i < MI; i++) {
                wmma::load_matrix_sync(ahi[i], &As[(wm + i * 16) * LDA_S + kk], LDA_S);
                #pragma unroll
                for (int e = 0; e < ahi[i].num_elements; e++) {
                    float f  = ahi[i].x[e];
                    float hi = wmma::__float_to_tf32(f);
                    ahi[i].x[e] = hi;
                    alo[i].x[e] = wmma::__float_to_tf32(f - hi);
                }
            }
            #pragma unroll
            for (int j = 0; j < NI; j++) {
                wmma::load_matrix_sync(bhi[j], &Bs[kk * LDB_S + wn + j * 16], LDB_S);
                #pragma unroll
                for (int e = 0; e < bhi[j].num_elements; e++) {
                    float f  = bhi[j].x[e];
                    float hi = wmma::__float_to_tf32(f);
                    bhi[j].x[e] = hi;
                    blo[j].x[e] = wmma::__float_to_tf32(f - hi);
                }
            }
            #pragma unroll
            for (int i = 0; i < MI; i++)
                #pragma unroll
                for (int j = 0; j < NI; j++) {
                    wmma::mma_sync(acc[i][j], ahi[i], bhi[j], acc[i][j]);
                    wmma::mma_sync(acc[i][j], alo[i], bhi[j], acc[i][j]);
                    wmma::mma_sync(acc[i][j], ahi[i], blo[j], acc[i][j]);
                }
        }
        __syncthreads();
    }

    // ---- epilogue: two waves share the (now dead) tile smem for staging ----
    float* stg = sm + (warp % MW) * (WM * LDS_T);
    #pragma unroll
    for (int wave = 0; wave < NW; ++wave) {
        if ((warp / MW) == wave) {
            #pragma unroll
            for (int i = 0; i < MI; i++)
                #pragma unroll
                for (int j = 0; j < NI; j++)
                    wmma::store_matrix_sync(&stg[(i * 16) * LDS_T + j * 16], acc[i][j],
                                            LDS_T, wmma::mem_row_major);
            __syncwarp();
            for (int idx = lane; idx < WM * WN; idx += 32) {
                int r  = idx / WN, c2 = idx % WN;
                int gr = bm + wm + r, gc = bn + wn + c2;
                float vv = stg[r * LDS_T + c2];
                if (bias) vv += bias[gc];
                if constexpr (EPI == 1) vv = gelu_f(vv);
                if constexpr (EPI == 2) vv += res[(long long)gr * ldc + gc];
                C[(long long)gr * ldc + gc] = vv;
            }
        }
        __syncthreads();
    }
}

// ---------------- LayerNorm: one row (D=1024) per block, 256 threads ----------
__global__ __launch_bounds__(256)
void ln_kernel(const float* __restrict__ x, const float* __restrict__ g,
               const float* __restrict__ b, float* __restrict__ o)
{
    __shared__ float shs[8], shs2[8], shbc[2];
    const int row = blockIdx.x;
    const float* xr = x + (long long)row * D_;
    float* orow     = o + (long long)row * D_;
    const int t = threadIdx.x;
    float v[4]; float s = 0.f, s2 = 0.f;
    #pragma unroll
    for (int i = 0; i < 4; i++) { v[i] = xr[t + i * 256]; s += v[i]; s2 += v[i] * v[i]; }
    #pragma unroll
    for (int off = 16; off; off >>= 1) {
        s  += __shfl_xor_sync(0xffffffffu, s,  off);
        s2 += __shfl_xor_sync(0xffffffffu, s2, off);
    }
    if ((t & 31) == 0) { shs[t >> 5] = s; shs2[t >> 5] = s2; }
    __syncthreads();
    if (t < 32) {
        s  = (t < 8) ? shs[t]  : 0.f;
        s2 = (t < 8) ? shs2[t] : 0.f;
        #pragma unroll
        for (int off = 4; off; off >>= 1) {
            s  += __shfl_xor_sync(0xffffffffu, s,  off);
            s2 += __shfl_xor_sync(0xffffffffu, s2, off);
        }
        if (t == 0) {
            float mu = s * (1.0f / D_);
            shbc[0] = mu;
            shbc[1] = rsqrtf(s2 * (1.0f / D_) - mu * mu + 1e-5f);
        }
    }
    __syncthreads();
    const float mu = shbc[0], inv = shbc[1];
    #pragma unroll
    for (int i = 0; i < 4; i++) {
        int c = t + i * 256;
        orow[c] = (v[i] - mu) * inv * g[c] + b[c];
    }
}

// ---------------- causal softmax over scores; scale 1/sqrt(64)=0.125 ----------
__global__ __launch_bounds__(256)
void softmax_kernel(float* __restrict__ S)
{
    __shared__ float red[8], bcast;
    const long long row = blockIdx.x;            // b*H*T rows
    const int q = (int)(row % T_);
    float* sr = S + row * (long long)T_;
    const int t = threadIdx.x;
    const int c0 = t * 4;
    float4 vv = *reinterpret_cast<float4*>(sr + c0);
    float val[4];
    val[0] = (c0 + 0 <= q) ? vv.x * 0.125f : -FLT_MAX;
    val[1] = (c0 + 1 <= q) ? vv.y * 0.125f : -FLT_MAX;
    val[2] = (c0 + 2 <= q) ? vv.z * 0.125f : -FLT_MAX;
    val[3] = (c0 + 3 <= q) ? vv.w * 0.125f : -FLT_MAX;
    float mx = fmaxf(fmaxf(val[0], val[1]), fmaxf(val[2], val[3]));
    #pragma unroll
    for (int off = 16; off; off >>= 1) mx = fmaxf(mx, __shfl_xor_sync(0xffffffffu, mx, off));
    if ((t & 31) == 0) red[t >> 5] = mx;
    __syncthreads();
    if (t == 0) {
        float m = red[0];
        #pragma unroll
        for (int i = 1; i < 8; i++) m = fmaxf(m, red[i]);
        bcast = m;
    }
    __syncthreads();
    mx = bcast;
    float e[4], s = 0.f;
    #pragma unroll
    for (int i = 0; i < 4; i++) { e[i] = expf(val[i] - mx); s += e[i]; }
    #pragma unroll
    for (int off = 16; off; off >>= 1) s += __shfl_xor_sync(0xffffffffu, s, off);
    __syncthreads();                 // red[] reuse
    if ((t & 31) == 0) red[t >> 5] = s;
    __syncthreads();
    if (t == 0) {
        float m = 0.f;
        #pragma unroll
        for (int i = 0; i < 8; i++) m += red[i];
        bcast = 1.0f / m;
    }
    __syncthreads();
    const float inv = bcast;
    vv.x = e[0] * inv; vv.y = e[1] * inv; vv.z = e[2] * inv; vv.w = e[3] * inv;
    *reinterpret_cast<float4*>(sr + c0) = vv;
}

// ---------------- embedding ---------------------------------------------------
__global__ __launch_bounds__(256)
void embed_kernel(const int* __restrict__ idx, const float* __restrict__ tok,
                  const float* __restrict__ pos, float* __restrict__ x)
{
    const int bt = blockIdx.x;
    const int tk = idx[bt];
    const int tt = bt % T_;
    const float* tr = tok + (long long)tk * D_;
    const float* pr = pos + (long long)tt * D_;
    float* xr = x + (long long)bt * D_;
    for (int i = threadIdx.x; i < D_; i += 256) xr[i] = tr[i] + pr[i];
}

// ---------------- host-side launcher wrapper ----------------------------------
template<int BM, int BN, int BK, int WM, int WN, bool BT, int EPI>
static void gemm(const float* A, const float* Bm, const float* bias, const float* res,
                 float* C, int M, int N, int K, int lda, int ldb, int ldc,
                 int batch = 1, int innerDiv = 1,
                 long long aO = 0, long long aI = 0,
                 long long bO = 0, long long bI = 0,
                 long long cO = 0, long long cI = 0)
{
    dim3 grid(N / BN, M / BM, batch);
    gemm_kernel<BM, BN, BK, WM, WN, BT, EPI><<<grid, 256>>>(
        A, Bm, bias, res, C, M, N, K, lda, ldb, ldc, innerDiv, aO, aI, bO, bI, cO, cI);
}

extern "C" void kernel_launch(void* const* d_in, const int* in_sizes, int n_in,
                              void* d_out, int out_size)
{
    (void)in_sizes; (void)n_in; (void)out_size;
    const int*   idx   = (const int*)  d_in[0];
    const float* tok   = (const float*)d_in[1];
    const float* pos   = (const float*)d_in[2];
    const float* ln1g  = (const float*)d_in[3];
    const float* ln1b  = (const float*)d_in[4];
    const float* Wq    = (const float*)d_in[5];
    const float* bq    = (const float*)d_in[6];
    const float* Wk    = (const float*)d_in[7];
    const float* bk    = (const float*)d_in[8];
    const float* Wv    = (const float*)d_in[9];
    const float* bv    = (const float*)d_in[10];
    const float* Wo    = (const float*)d_in[11];
    const float* bo    = (const float*)d_in[12];
    const float* ln2g  = (const float*)d_in[13];
    const float* ln2b  = (const float*)d_in[14];
    const float* W1    = (const float*)d_in[15];
    const float* b1    = (const float*)d_in[16];
    const float* W2    = (const float*)d_in[17];
    const float* b2    = (const float*)d_in[18];
    const float* lnfg  = (const float*)d_in[19];
    const float* lnfb  = (const float*)d_in[20];
    const float* Wh    = (const float*)d_in[21];
    const float* bh    = (const float*)d_in[22];

    float *x, *h, *q, *k, *v, *o, *ff, *s;
    cudaGetSymbolAddress((void**)&x,  g_x);
    cudaGetSymbolAddress((void**)&h,  g_h);
    cudaGetSymbolAddress((void**)&q,  g_q);
    cudaGetSymbolAddress((void**)&k,  g_k);
    cudaGetSymbolAddress((void**)&v,  g_v);
    cudaGetSymbolAddress((void**)&o,  g_o);
    cudaGetSymbolAddress((void**)&ff, g_ff);
    cudaGetSymbolAddress((void**)&s,  g_s);

    embed_kernel<<<M_, 256>>>(idx, tok, pos, x);

    for (int l = 0; l < L_; ++l) {
        const float* Wq_l = Wq + (size_t)l * D_ * D_;
        const float* Wk_l = Wk + (size_t)l * D_ * D_;
        const float* Wv_l = Wv + (size_t)l * D_ * D_;
        const float* Wo_l = Wo + (size_t)l * D_ * D_;
        const float* W1_l = W1 + (size_t)l * D_ * FF_;
        const float* W2_l = W2 + (size_t)l * FF_ * D_;

        // ln1 -> h
        ln_kernel<<<M_, 256>>>(x, ln1g + (size_t)l * D_, ln1b + (size_t)l * D_, h);

        // q, k, v projections
        gemm<128,128,32,32,64,false,0>(h, Wq_l, bq + (size_t)l * D_, nullptr, q, M_, D_, D_, D_, D_, D_);
        gemm<128,128,32,32,64,false,0>(h, Wk_l, bk + (size_t)l * D_, nullptr, k, M_, D_, D_, D_, D_, D_);
        gemm<128,128,32,32,64,false,0>(h, Wv_l, bv + (size_t)l * D_, nullptr, v, M_, D_, D_, D_, D_, D_);

        // scores S[b,h] = Q_bh @ K_bh^T   (batched NT, K=DH)
        gemm<128,128,32,32,64,true,0>(q, k, nullptr, nullptr, s,
            T_, T_, DH_, D_, D_, T_,
            B_ * H_, H_,
            (long long)T_ * D_, (long long)DH_,
            (long long)T_ * D_, (long long)DH_,
            (long long)H_ * T_ * T_, (long long)T_ * T_);

        // causal softmax in-place
        softmax_kernel<<<B_ * H_ * T_, 256>>>(s);

        // O[b,h] = P @ V_bh  (batched NN, N=DH)
        gemm<128,64,32,32,32,false,0>(s, v, nullptr, nullptr, o,
            T_, DH_, T_, T_, D_, D_,
            B_ * H_, H_,
            (long long)H_ * T_ * T_, (long long)T_ * T_,
            (long long)T_ * D_, (long long)DH_,
            (long long)T_ * D_, (long long)DH_);

        // x = x + O @ Wo + bo
        gemm<128,128,32,32,64,false,2>(o, Wo_l, bo + (size_t)l * D_, x, x, M_, D_, D_, D_, D_, D_);

        // ln2 -> h
        ln_kernel<<<M_, 256>>>(x, ln2g + (size_t)l * D_, ln2b + (size_t)l * D_, h);

        // ff = gelu(h @ W1 + b1)
        gemm<128,128,32,32,64,false,1>(h, W1_l, b1 + (size_t)l * FF_, nullptr, ff, M_, FF_, D_, D_, FF_, FF_);

        // x = x + ff @ W2 + b2
        gemm<128,128,32,32,64,false,2>(ff, W2_l, b2 + (size_t)l * D_, x, x, M_, D_, FF_, FF_, D_, D_);
    }

    // final LN + head
    ln_kernel<<<M_, 256>>>(x, lnfg, lnfb, h);
    gemm<128,128,32,32,64,false,0>(h, Wh, bh, nullptr, (float*)d_out, M_, V_, D_, D_, V_, V_);
}

// round 8
// speedup vs baseline: 3.3636x; 3.3636x over previous
#include <cuda_runtime.h>
#include <cuda_bf16.h>
#include <mma.h>
#include <cfloat>
#include <cstdint>

using namespace nvcuda;

#define L_  8
#define D_  1024
#define H_  16
#define T_  1024
#define V_  2048
#define B_  8
#define DH_ 64
#define FF_ 4096
#define M_  (B_ * T_)   // 8192 rows

// ---------------- scratch (device globals; no allocation allowed) -------------
__device__ float g_x [ (size_t)M_ * D_ ];
__device__ float g_h [ (size_t)M_ * D_ ];
__device__ float g_q [ (size_t)M_ * D_ ];
__device__ float g_k [ (size_t)M_ * D_ ];
__device__ float g_v [ (size_t)M_ * D_ ];
__device__ float g_o [ (size_t)M_ * D_ ];
__device__ float g_ff[ (size_t)M_ * FF_ ];
__device__ float g_s [ (size_t)B_ * H_ * T_ * T_ ];   // 512 MB attention scores

// Transposed + bf16-split weights: [N,K] K-major, hi and lo parts.
// total elems = 8*(4*D*D + D*FF + FF*D) + D*V = 102,760,448
#define WTOT 102760448ULL
__device__ __nv_bfloat16 g_whi[WTOT];
__device__ __nv_bfloat16 g_wlo[WTOT];

// ---------------- helpers ----------------------------------------------------
__device__ __forceinline__ float gelu_f(float x) {
    return 0.5f * x * (1.0f + erff(x * 0.70710678118654752f));
}

// RN split of a float4 into packed bf16x2 hi and lo pairs.
__device__ __forceinline__ void split4(float4 f4, uint2& hi, uint2& lo) {
    unsigned h01, h23;
    asm("cvt.rn.bf16x2.f32 %0, %1, %2;" : "=r"(h01) : "f"(f4.y), "f"(f4.x));
    asm("cvt.rn.bf16x2.f32 %0, %1, %2;" : "=r"(h23) : "f"(f4.w), "f"(f4.z));
    float hx = __uint_as_float(h01 << 16);
    float hy = __uint_as_float(h01 & 0xffff0000u);
    float hz = __uint_as_float(h23 << 16);
    float hw = __uint_as_float(h23 & 0xffff0000u);
    float lx = f4.x - hx, ly = f4.y - hy, lz = f4.z - hz, lw = f4.w - hw;
    unsigned l01, l23;
    asm("cvt.rn.bf16x2.f32 %0, %1, %2;" : "=r"(l01) : "f"(ly), "f"(lx));
    asm("cvt.rn.bf16x2.f32 %0, %1, %2;" : "=r"(l23) : "f"(lw), "f"(lz));
    hi = make_uint2(h01, h23);
    lo = make_uint2(l01, l23);
}

// =============================================================================
// Weight transpose + bf16 RN-split:  W[K,N] fp32 -> hi/lo [N,K] bf16.
// =============================================================================
__global__ __launch_bounds__(256)
void wsplit_kernel(const float* __restrict__ W, __nv_bfloat16* __restrict__ hi,
                   __nv_bfloat16* __restrict__ lo, int K, int N)
{
    __shared__ float t[32][33];
    const int k0 = blockIdx.y * 32, n0 = blockIdx.x * 32;
    const int tx = threadIdx.x & 31, ty = threadIdx.x >> 5;
    #pragma unroll
    for (int r = ty; r < 32; r += 8)
        t[r][tx] = W[(long long)(k0 + r) * N + n0 + tx];
    __syncthreads();
    #pragma unroll
    for (int r = ty; r < 32; r += 8) {
        float f = t[tx][r];                       // = W[k0+tx][n0+r]
        __nv_bfloat16 hb = __float2bfloat16(f);   // RN
        long long o = (long long)(n0 + r) * K + k0 + tx;
        hi[o] = hb;
        lo[o] = __float2bfloat16(f - __bfloat162float(hb));
    }
}

// =============================================================================
// bf16 2-term-split wmma GEMM (mma.sync m16n16k16, plain PTX — no 'a' features)
//   C = A(MxK, fp32) * B(KxN) [+bias] [+gelu | +residual]
// BMODE: 0 = B fp32 [K,N] (n-contig, row_major)      — PV     (ldb = N-row stride)
//        1 = B fp32 [N,K] (k-contig, col_major)      — Q K^T  (ldb = K-row stride)
//        2 = B pre-split bf16 hi/lo [N,K] (col_major)— weights (ldb MUST be K)
// Batched via blockIdx.z: off = (z/innerDiv)*sOuter + (z%innerDiv)*sInner
// All dims divide tiles. 256 threads, 2 CTAs/SM.
// =============================================================================
template<int BM, int BN, int BK, int WM, int WN, int BMODE, int EPI>
__global__ __launch_bounds__(256, 2)
void gemm_bf(const float* __restrict__ A, const void* __restrict__ B0v,
             const void* __restrict__ B1v, const float* __restrict__ bias,
             const float* __restrict__ res, float* __restrict__ C,
             int M, int N, int K, int lda, int ldb, int ldc,
             int innerDiv,
             long long aOut, long long aIn,
             long long bOut, long long bIn,
             long long cOut, long long cIn)
{
    constexpr int MW = BM / WM;
    constexpr int NW = BN / WN;
    static_assert(MW * NW == 8, "expect 256 threads");
    constexpr int LDA_S = BK + 8;                   // halves
    constexpr int LDB_S = BN + 8;                   // halves (BMODE0 only)
    constexpr int MI = WM / 16;
    constexpr int NI = WN / 16;
    constexpr int BPART = (BMODE == 0) ? BK * LDB_S : BN * LDA_S;

    extern __shared__ __align__(16) char smraw[];
    __nv_bfloat16* Ah = (__nv_bfloat16*)smraw;
    __nv_bfloat16* Al = Ah + BM * LDA_S;
    __nv_bfloat16* Bh = Al + BM * LDA_S;
    __nv_bfloat16* Bl = Bh + BPART;

    const int z = blockIdx.z;
    const long long offA = (long long)(z / innerDiv) * aOut + (long long)(z % innerDiv) * aIn;
    const long long offB = (long long)(z / innerDiv) * bOut + (long long)(z % innerDiv) * bIn;
    const long long offC = (long long)(z / innerDiv) * cOut + (long long)(z % innerDiv) * cIn;
    A += offA;
    C += offC;
    if constexpr (EPI == 2) res += offC;

    const int bm   = blockIdx.y * BM;
    const int bn   = blockIdx.x * BN;
    const int tid  = threadIdx.x;
    const int warp = tid >> 5;
    const int lane = tid & 31;
    const int wm   = (warp % MW) * WM;
    const int wn   = (warp / MW) * WN;

    wmma::fragment<wmma::accumulator, 16, 16, 16, float> acc[MI][NI];
    #pragma unroll
    for (int i = 0; i < MI; i++)
        #pragma unroll
        for (int j = 0; j < NI; j++)
            wmma::fill_fragment(acc[i][j], 0.0f);

    for (int k0 = 0; k0 < K; k0 += BK) {
        // ---- stage A: fp32 -> bf16 hi/lo ----
        {
            constexpr int SLOTS = BM * (BK / 4);
            #pragma unroll
            for (int p = 0; p < SLOTS / 256; ++p) {
                int i = tid + p * 256;
                int m = i / (BK / 4);
                int q = i % (BK / 4);
                float4 f4 = *(const float4*)(A + (long long)(bm + m) * lda + k0 + q * 4);
                uint2 hi, lo;
                split4(f4, hi, lo);
                *(uint2*)(Ah + m * LDA_S + q * 4) = hi;
                *(uint2*)(Al + m * LDA_S + q * 4) = lo;
            }
        }
        // ---- stage B ----
        if constexpr (BMODE == 2) {
            const __nv_bfloat16* Bhg = (const __nv_bfloat16*)B0v + offB;
            const __nv_bfloat16* Blg = (const __nv_bfloat16*)B1v + offB;
            constexpr int SLOTS = BN * (BK / 8);
            #pragma unroll
            for (int p = 0; p < SLOTS / 256; ++p) {
                int i = tid + p * 256;
                int n = i / (BK / 8);
                int q = i % (BK / 8);
                *(uint4*)(Bh + n * LDA_S + q * 8) =
                    *(const uint4*)(Bhg + (long long)(bn + n) * ldb + k0 + q * 8);
                *(uint4*)(Bl + n * LDA_S + q * 8) =
                    *(const uint4*)(Blg + (long long)(bn + n) * ldb + k0 + q * 8);
            }
        } else if constexpr (BMODE == 1) {
            const float* Bg = (const float*)B0v + offB;
            constexpr int SLOTS = BN * (BK / 4);
            #pragma unroll
            for (int p = 0; p < SLOTS / 256; ++p) {
                int i = tid + p * 256;
                int n = i / (BK / 4);
                int q = i % (BK / 4);
                float4 f4 = *(const float4*)(Bg + (long long)(bn + n) * ldb + k0 + q * 4);
                uint2 hi, lo;
                split4(f4, hi, lo);
                *(uint2*)(Bh + n * LDA_S + q * 4) = hi;
                *(uint2*)(Bl + n * LDA_S + q * 4) = lo;
            }
        } else {
            const float* Bg = (const float*)B0v + offB;
            constexpr int SLOTS = BK * (BN / 4);
            #pragma unroll
            for (int p = 0; p < SLOTS / 256; ++p) {
                int i = tid + p * 256;
                int k = i / (BN / 4);
                int q = i % (BN / 4);
                float4 f4 = *(const float4*)(Bg + (long long)(k0 + k) * ldb + bn + q * 4);
                uint2 hi, lo;
                split4(f4, hi, lo);
                *(uint2*)(Bh + k * LDB_S + q * 4) = hi;
                *(uint2*)(Bl + k * LDB_S + q * 4) = lo;
            }
        }
        __syncthreads();

        // ---- MMA mainloop: pure LDSM + HMMA ----
        #pragma unroll
        for (int kk = 0; kk < BK; kk += 16) {
            wmma::fragment<wmma::matrix_a, 16, 16, 16, __nv_bfloat16, wmma::row_major> ahi[MI], alo[MI];
            #pragma unroll
            for (int i = 0; i < MI; i++) {
                wmma::load_matrix_sync(ahi[i], Ah + (wm + i * 16) * LDA_S + kk, LDA_S);
                wmma::load_matrix_sync(alo[i], Al + (wm + i * 16) * LDA_S + kk, LDA_S);
            }
            #pragma unroll
            for (int j = 0; j < NI; j++) {
                if constexpr (BMODE == 0) {
                    wmma::fragment<wmma::matrix_b, 16, 16, 16, __nv_bfloat16, wmma::row_major> bhi, blo;
                    wmma::load_matrix_sync(bhi, Bh + kk * LDB_S + wn + j * 16, LDB_S);
                    wmma::load_matrix_sync(blo, Bl + kk * LDB_S + wn + j * 16, LDB_S);
                    #pragma unroll
                    for (int i = 0; i < MI; i++) {
                        wmma::mma_sync(acc[i][j], ahi[i], bhi, acc[i][j]);
                        wmma::mma_sync(acc[i][j], alo[i], bhi, acc[i][j]);
                        wmma::mma_sync(acc[i][j], ahi[i], blo, acc[i][j]);
                    }
                } else {
                    wmma::fragment<wmma::matrix_b, 16, 16, 16, __nv_bfloat16, wmma::col_major> bhi, blo;
                    wmma::load_matrix_sync(bhi, Bh + (wn + j * 16) * LDA_S + kk, LDA_S);
                    wmma::load_matrix_sync(blo, Bl + (wn + j * 16) * LDA_S + kk, LDA_S);
                    #pragma unroll
                    for (int i = 0; i < MI; i++) {
                        wmma::mma_sync(acc[i][j], ahi[i], bhi, acc[i][j]);
                        wmma::mma_sync(acc[i][j], alo[i], bhi, acc[i][j]);
                        wmma::mma_sync(acc[i][j], ahi[i], blo, acc[i][j]);
                    }
                }
            }
        }
        __syncthreads();
    }

    // ---- epilogue: stage per-warp tile in (dead) smem, vector-ish store ----
    constexpr int LDS_T = WN + 4;
    float* stg = (float*)smraw + (warp % MW) * (WM * LDS_T);
    #pragma unroll
    for (int wave = 0; wave < NW; ++wave) {
        if ((warp / MW) == wave) {
            #pragma unroll
            for (int i = 0; i < MI; i++)
                #pragma unroll
                for (int j = 0; j < NI; j++)
                    wmma::store_matrix_sync(&stg[(i * 16) * LDS_T + j * 16], acc[i][j],
                                            LDS_T, wmma::mem_row_major);
            __syncwarp();
            for (int idx = lane; idx < WM * WN; idx += 32) {
                int r  = idx / WN, c2 = idx % WN;
                int gr = bm + wm + r, gc = bn + wn + c2;
                float vv = stg[r * LDS_T + c2];
                if (bias) vv += bias[gc];
                if constexpr (EPI == 1) vv = gelu_f(vv);
                if constexpr (EPI == 2) vv += res[(long long)gr * ldc + gc];
                C[(long long)gr * ldc + gc] = vv;
            }
        }
        __syncthreads();
    }
}

// ---------------- LayerNorm ----------------------------------------------------
__global__ __launch_bounds__(256)
void ln_kernel(const float* __restrict__ x, const float* __restrict__ g,
               const float* __restrict__ b, float* __restrict__ o)
{
    __shared__ float shs[8], shs2[8], shbc[2];
    const int row = blockIdx.x;
    const float* xr = x + (long long)row * D_;
    float* orow     = o + (long long)row * D_;
    const int t = threadIdx.x;
    float v[4]; float s = 0.f, s2 = 0.f;
    #pragma unroll
    for (int i = 0; i < 4; i++) { v[i] = xr[t + i * 256]; s += v[i]; s2 += v[i] * v[i]; }
    #pragma unroll
    for (int off = 16; off; off >>= 1) {
        s  += __shfl_xor_sync(0xffffffffu, s,  off);
        s2 += __shfl_xor_sync(0xffffffffu, s2, off);
    }
    if ((t & 31) == 0) { shs[t >> 5] = s; shs2[t >> 5] = s2; }
    __syncthreads();
    if (t < 32) {
        s  = (t < 8) ? shs[t]  : 0.f;
        s2 = (t < 8) ? shs2[t] : 0.f;
        #pragma unroll
        for (int off = 4; off; off >>= 1) {
            s  += __shfl_xor_sync(0xffffffffu, s,  off);
            s2 += __shfl_xor_sync(0xffffffffu, s2, off);
        }
        if (t == 0) {
            float mu = s * (1.0f / D_);
            shbc[0] = mu;
            shbc[1] = rsqrtf(s2 * (1.0f / D_) - mu * mu + 1e-5f);
        }
    }
    __syncthreads();
    const float mu = shbc[0], inv = shbc[1];
    #pragma unroll
    for (int i = 0; i < 4; i++) {
        int c = t + i * 256;
        orow[c] = (v[i] - mu) * inv * g[c] + b[c];
    }
}

// ---------------- causal softmax ----------------------------------------------
__global__ __launch_bounds__(256)
void softmax_kernel(float* __restrict__ S)
{
    __shared__ float red[8], bcast;
    const long long row = blockIdx.x;
    const int q = (int)(row % T_);
    float* sr = S + row * (long long)T_;
    const int t = threadIdx.x;
    const int c0 = t * 4;
    float4 vv = *reinterpret_cast<float4*>(sr + c0);
    float val[4];
    val[0] = (c0 + 0 <= q) ? vv.x * 0.125f : -FLT_MAX;
    val[1] = (c0 + 1 <= q) ? vv.y * 0.125f : -FLT_MAX;
    val[2] = (c0 + 2 <= q) ? vv.z * 0.125f : -FLT_MAX;
    val[3] = (c0 + 3 <= q) ? vv.w * 0.125f : -FLT_MAX;
    float mx = fmaxf(fmaxf(val[0], val[1]), fmaxf(val[2], val[3]));
    #pragma unroll
    for (int off = 16; off; off >>= 1) mx = fmaxf(mx, __shfl_xor_sync(0xffffffffu, mx, off));
    if ((t & 31) == 0) red[t >> 5] = mx;
    __syncthreads();
    if (t == 0) {
        float m = red[0];
        #pragma unroll
        for (int i = 1; i < 8; i++) m = fmaxf(m, red[i]);
        bcast = m;
    }
    __syncthreads();
    mx = bcast;
    float e[4], s = 0.f;
    #pragma unroll
    for (int i = 0; i < 4; i++) { e[i] = expf(val[i] - mx); s += e[i]; }
    #pragma unroll
    for (int off = 16; off; off >>= 1) s += __shfl_xor_sync(0xffffffffu, s, off);
    __syncthreads();
    if ((t & 31) == 0) red[t >> 5] = s;
    __syncthreads();
    if (t == 0) {
        float m = 0.f;
        #pragma unroll
        for (int i = 0; i < 8; i++) m += red[i];
        bcast = 1.0f / m;
    }
    __syncthreads();
    const float inv = bcast;
    vv.x = e[0] * inv; vv.y = e[1] * inv; vv.z = e[2] * inv; vv.w = e[3] * inv;
    *reinterpret_cast<float4*>(sr + c0) = vv;
}

// ---------------- embedding ---------------------------------------------------
__global__ __launch_bounds__(256)
void embed_kernel(const int* __restrict__ idx, const float* __restrict__ tok,
                  const float* __restrict__ pos, float* __restrict__ x)
{
    const int bt = blockIdx.x;
    const int tk = idx[bt];
    const int tt = bt % T_;
    const float* tr = tok + (long long)tk * D_;
    const float* pr = pos + (long long)tt * D_;
    float* xr = x + (long long)bt * D_;
    for (int i = threadIdx.x; i < D_; i += 256) xr[i] = tr[i] + pr[i];
}

// ---------------- host wrappers -----------------------------------------------
#define GEMM_SMEM 73728   // covers all configs

template<int BM, int BN, int BK, int WM, int WN, int BMODE, int EPI>
static void gemm(const float* A, const void* B0, const void* B1,
                 const float* bias, const float* res, float* C,
                 int M, int N, int K, int lda, int ldb, int ldc,
                 int batch = 1, int innerDiv = 1,
                 long long aO = 0, long long aI = 0,
                 long long bO = 0, long long bI = 0,
                 long long cO = 0, long long cI = 0)
{
    static bool init = false;
    if (!init) {
        cudaFuncSetAttribute(gemm_bf<BM, BN, BK, WM, WN, BMODE, EPI>,
                             cudaFuncAttributeMaxDynamicSharedMemorySize, GEMM_SMEM);
        init = true;
    }
    dim3 grid(N / BN, M / BM, batch);
    gemm_bf<BM, BN, BK, WM, WN, BMODE, EPI><<<grid, 256, GEMM_SMEM>>>(
        A, B0, B1, bias, res, C, M, N, K, lda, ldb, ldc, innerDiv, aO, aI, bO, bI, cO, cI);
}

extern "C" void kernel_launch(void* const* d_in, const int* in_sizes, int n_in,
                              void* d_out, int out_size)
{
    (void)in_sizes; (void)n_in; (void)out_size;
    const int*   idx   = (const int*)  d_in[0];
    const float* tok   = (const float*)d_in[1];
    const float* pos   = (const float*)d_in[2];
    const float* ln1g  = (const float*)d_in[3];
    const float* ln1b  = (const float*)d_in[4];
    const float* Wq    = (const float*)d_in[5];
    const float* bq    = (const float*)d_in[6];
    const float* Wk    = (const float*)d_in[7];
    const float* bk    = (const float*)d_in[8];
    const float* Wv    = (const float*)d_in[9];
    const float* bv    = (const float*)d_in[10];
    const float* Wo    = (const float*)d_in[11];
    const float* bo    = (const float*)d_in[12];
    const float* ln2g  = (const float*)d_in[13];
    const float* ln2b  = (const float*)d_in[14];
    const float* W1    = (const float*)d_in[15];
    const float* b1    = (const float*)d_in[16];
    const float* W2    = (const float*)d_in[17];
    const float* b2    = (const float*)d_in[18];
    const float* lnfg  = (const float*)d_in[19];
    const float* lnfb  = (const float*)d_in[20];
    const float* Wh    = (const float*)d_in[21];
    const float* bh    = (const float*)d_in[22];

    float *x, *h, *q, *k, *v, *o, *ff, *s;
    __nv_bfloat16 *whi, *wlo;
    cudaGetSymbolAddress((void**)&x,   g_x);
    cudaGetSymbolAddress((void**)&h,   g_h);
    cudaGetSymbolAddress((void**)&q,   g_q);
    cudaGetSymbolAddress((void**)&k,   g_k);
    cudaGetSymbolAddress((void**)&v,   g_v);
    cudaGetSymbolAddress((void**)&o,   g_o);
    cudaGetSymbolAddress((void**)&ff,  g_ff);
    cudaGetSymbolAddress((void**)&s,   g_s);
    cudaGetSymbolAddress((void**)&whi, g_whi);
    cudaGetSymbolAddress((void**)&wlo, g_wlo);

    // -------- weight transpose + split (captured in graph; runs every replay) --
    const size_t WD = (size_t)D_ * D_;
    const size_t LW = 4 * WD + (size_t)D_ * FF_ + (size_t)FF_ * D_;   // per-layer
    for (int l = 0; l < L_; ++l) {
        size_t base = (size_t)l * LW;
        wsplit_kernel<<<dim3(D_ / 32, D_ / 32), 256>>>(Wq + (size_t)l * WD, whi + base,          wlo + base,          D_, D_);
        wsplit_kernel<<<dim3(D_ / 32, D_ / 32), 256>>>(Wk + (size_t)l * WD, whi + base + WD,     wlo + base + WD,     D_, D_);
        wsplit_kernel<<<dim3(D_ / 32, D_ / 32), 256>>>(Wv + (size_t)l * WD, whi + base + 2 * WD, wlo + base + 2 * WD, D_, D_);
        wsplit_kernel<<<dim3(D_ / 32, D_ / 32), 256>>>(Wo + (size_t)l * WD, whi + base + 3 * WD, wlo + base + 3 * WD, D_, D_);
        wsplit_kernel<<<dim3(FF_ / 32, D_ / 32), 256>>>(W1 + (size_t)l * D_ * FF_, whi + base + 4 * WD,                    wlo + base + 4 * WD,                    D_, FF_);
        wsplit_kernel<<<dim3(D_ / 32, FF_ / 32), 256>>>(W2 + (size_t)l * FF_ * D_, whi + base + 4 * WD + (size_t)D_ * FF_, wlo + base + 4 * WD + (size_t)D_ * FF_, FF_, D_);
    }
    const size_t off_wh = 8 * LW;
    wsplit_kernel<<<dim3(V_ / 32, D_ / 32), 256>>>(Wh, whi + off_wh, wlo + off_wh, D_, V_);

    embed_kernel<<<M_, 256>>>(idx, tok, pos, x);

    for (int l = 0; l < L_; ++l) {
        size_t base = (size_t)l * LW;
        const __nv_bfloat16 *qh = whi + base,          *ql = wlo + base;
        const __nv_bfloat16 *kh = whi + base + WD,     *kl = wlo + base + WD;
        const __nv_bfloat16 *vh = whi + base + 2 * WD, *vl = wlo + base + 2 * WD;
        const __nv_bfloat16 *oh = whi + base + 3 * WD, *ol = wlo + base + 3 * WD;
        const __nv_bfloat16 *w1h = whi + base + 4 * WD,                    *w1l = wlo + base + 4 * WD;
        const __nv_bfloat16 *w2h = whi + base + 4 * WD + (size_t)D_ * FF_, *w2l = wlo + base + 4 * WD + (size_t)D_ * FF_;

        // ln1 -> h
        ln_kernel<<<M_, 256>>>(x, ln1g + (size_t)l * D_, ln1b + (size_t)l * D_, h);

        // q, k, v projections (dense, pre-split weights; ldb = K = D_)
        gemm<128,128,64,32,64,2,0>(h, qh, ql, bq + (size_t)l * D_, nullptr, q, M_, D_, D_, D_, D_, D_);
        gemm<128,128,64,32,64,2,0>(h, kh, kl, bk + (size_t)l * D_, nullptr, k, M_, D_, D_, D_, D_, D_);
        gemm<128,128,64,32,64,2,0>(h, vh, vl, bv + (size_t)l * D_, nullptr, v, M_, D_, D_, D_, D_, D_);

        // scores S[b,h] = Q_bh @ K_bh^T   (batched, B as [N,K] fp32, ldb = D_)
        gemm<128,128,64,32,64,1,0>(q, k, nullptr, nullptr, nullptr, s,
            T_, T_, DH_, D_, D_, T_,
            B_ * H_, H_,
            (long long)T_ * D_, (long long)DH_,
            (long long)T_ * D_, (long long)DH_,
            (long long)H_ * T_ * T_, (long long)T_ * T_);

        softmax_kernel<<<B_ * H_ * T_, 256>>>(s);

        // O[b,h] = P @ V_bh  (batched, B as [K,N] fp32, ldb = D_)
        gemm<128,64,64,32,32,0,0>(s, v, nullptr, nullptr, nullptr, o,
            T_, DH_, T_, T_, D_, D_,
            B_ * H_, H_,
            (long long)H_ * T_ * T_, (long long)T_ * T_,
            (long long)T_ * D_, (long long)DH_,
            (long long)T_ * D_, (long long)DH_);

        // x = x + O @ Wo + bo   (ldb = K = D_)
        gemm<128,128,64,32,64,2,2>(o, oh, ol, bo + (size_t)l * D_, x, x, M_, D_, D_, D_, D_, D_);

        // ln2 -> h
        ln_kernel<<<M_, 256>>>(x, ln2g + (size_t)l * D_, ln2b + (size_t)l * D_, h);

        // ff = gelu(h @ W1 + b1)   (FIX: ldb = K = D_, not FF_)
        gemm<128,128,64,32,64,2,1>(h, w1h, w1l, b1 + (size_t)l * FF_, nullptr, ff, M_, FF_, D_, D_, D_, FF_);

        // x = x + ff @ W2 + b2     (FIX: ldb = K = FF_, not D_)
        gemm<128,128,64,32,64,2,2>(ff, w2h, w2l, b2 + (size_t)l * D_, x, x, M_, D_, FF_, FF_, FF_, D_);
    }

    // final LN + head             (FIX: ldb = K = D_, not V_)
    ln_kernel<<<M_, 256>>>(x, lnfg, lnfb, h);
    gemm<128,128,64,32,64,2,0>(h, whi + off_wh, wlo + off_wh, bh, nullptr, (float*)d_out, M_, V_, D_, D_, D_, V_);
}

// round 9
// speedup vs baseline: 3.9191x; 1.1652x over previous
#include <cuda_runtime.h>
#include <cuda_bf16.h>
#include <mma.h>
#include <cfloat>
#include <cstdint>

using namespace nvcuda;

#define L_  8
#define D_  1024
#define H_  16
#define T_  1024
#define V_  2048
#define B_  8
#define DH_ 64
#define FF_ 4096
#define M_  (B_ * T_)   // 8192 rows

// ---------------- scratch (device globals; no allocation allowed) -------------
__device__ float g_x [ (size_t)M_ * D_ ];
__device__ float g_h [ (size_t)M_ * D_ ];
__device__ float g_q [ (size_t)M_ * D_ ];
__device__ float g_k [ (size_t)M_ * D_ ];
__device__ float g_v [ (size_t)M_ * D_ ];
__device__ float g_o [ (size_t)M_ * D_ ];
__device__ float g_ff[ (size_t)M_ * FF_ ];

// Transposed + bf16-split weights: [N,K] K-major, hi and lo parts.
#define WTOT 102760448ULL
__device__ __nv_bfloat16 g_whi[WTOT];
__device__ __nv_bfloat16 g_wlo[WTOT];

// ---------------- helpers ----------------------------------------------------
__device__ __forceinline__ float gelu_f(float x) {
    return 0.5f * x * (1.0f + erff(x * 0.70710678118654752f));
}

// RN split of a float4 into packed bf16x2 hi and lo pairs.
__device__ __forceinline__ void split4(float4 f4, uint2& hi, uint2& lo) {
    unsigned h01, h23;
    asm("cvt.rn.bf16x2.f32 %0, %1, %2;" : "=r"(h01) : "f"(f4.y), "f"(f4.x));
    asm("cvt.rn.bf16x2.f32 %0, %1, %2;" : "=r"(h23) : "f"(f4.w), "f"(f4.z));
    float hx = __uint_as_float(h01 << 16);
    float hy = __uint_as_float(h01 & 0xffff0000u);
    float hz = __uint_as_float(h23 << 16);
    float hw = __uint_as_float(h23 & 0xffff0000u);
    float lx = f4.x - hx, ly = f4.y - hy, lz = f4.z - hz, lw = f4.w - hw;
    unsigned l01, l23;
    asm("cvt.rn.bf16x2.f32 %0, %1, %2;" : "=r"(l01) : "f"(ly), "f"(lx));
    asm("cvt.rn.bf16x2.f32 %0, %1, %2;" : "=r"(l23) : "f"(lw), "f"(lz));
    hi = make_uint2(h01, h23);
    lo = make_uint2(l01, l23);
}

// pack two floats into bf16x2 hi + residual lo
__device__ __forceinline__ void pack_split2(float x, float y, uint32_t& h, uint32_t& l) {
    asm("cvt.rn.bf16x2.f32 %0, %1, %2;" : "=r"(h) : "f"(y), "f"(x));
    float hx = __uint_as_float(h << 16);
    float hy = __uint_as_float(h & 0xffff0000u);
    asm("cvt.rn.bf16x2.f32 %0, %1, %2;" : "=r"(l) : "f"(y - hy), "f"(x - hx));
}

// raw bf16 mma m16n8k16 (acc layout architecturally specified)
__device__ __forceinline__ void mma16816(float* c, const uint32_t* a, uint32_t b0, uint32_t b1) {
    asm volatile("mma.sync.aligned.m16n8k16.row.col.f32.bf16.bf16.f32 "
        "{%0,%1,%2,%3}, {%4,%5,%6,%7}, {%8,%9}, {%0,%1,%2,%3};"
        : "+f"(c[0]), "+f"(c[1]), "+f"(c[2]), "+f"(c[3])
        : "r"(a[0]), "r"(a[1]), "r"(a[2]), "r"(a[3]), "r"(b0), "r"(b1));
}

// =============================================================================
// Weight transpose + bf16 RN-split:  W[K,N] fp32 -> hi/lo [N,K] bf16.
// =============================================================================
__global__ __launch_bounds__(256)
void wsplit_kernel(const float* __restrict__ W, __nv_bfloat16* __restrict__ hi,
                   __nv_bfloat16* __restrict__ lo, int K, int N)
{
    __shared__ float t[32][33];
    const int k0 = blockIdx.y * 32, n0 = blockIdx.x * 32;
    const int tx = threadIdx.x & 31, ty = threadIdx.x >> 5;
    #pragma unroll
    for (int r = ty; r < 32; r += 8)
        t[r][tx] = W[(long long)(k0 + r) * N + n0 + tx];
    __syncthreads();
    #pragma unroll
    for (int r = ty; r < 32; r += 8) {
        float f = t[tx][r];
        __nv_bfloat16 hb = __float2bfloat16(f);
        long long o = (long long)(n0 + r) * K + k0 + tx;
        hi[o] = hb;
        lo[o] = __float2bfloat16(f - __bfloat162float(hb));
    }
}

// =============================================================================
// bf16 2-term-split wmma GEMM — dense path (weights pre-split [N,K], ldb = K)
// EPI: 0 = +bias, 1 = +bias,gelu, 2 = +bias,+residual
// =============================================================================
template<int BM, int BN, int BK, int WM, int WN, int EPI>
__global__ __launch_bounds__(256, 2)
void gemm_bf(const float* __restrict__ A, const __nv_bfloat16* __restrict__ Bhg,
             const __nv_bfloat16* __restrict__ Blg, const float* __restrict__ bias,
             const float* __restrict__ res, float* __restrict__ C,
             int M, int N, int K, int lda, int ldb, int ldc)
{
    constexpr int MW = BM / WM;
    constexpr int NW = BN / WN;
    static_assert(MW * NW == 8, "expect 256 threads");
    constexpr int LDA_S = BK + 8;
    constexpr int MI = WM / 16;
    constexpr int NI = WN / 16;

    extern __shared__ __align__(16) char smraw[];
    __nv_bfloat16* Ah = (__nv_bfloat16*)smraw;
    __nv_bfloat16* Al = Ah + BM * LDA_S;
    __nv_bfloat16* Bh = Al + BM * LDA_S;
    __nv_bfloat16* Bl = Bh + BN * LDA_S;

    const int bm   = blockIdx.y * BM;
    const int bn   = blockIdx.x * BN;
    const int tid  = threadIdx.x;
    const int warp = tid >> 5;
    const int lane = tid & 31;
    const int wm   = (warp % MW) * WM;
    const int wn   = (warp / MW) * WN;

    wmma::fragment<wmma::accumulator, 16, 16, 16, float> acc[MI][NI];
    #pragma unroll
    for (int i = 0; i < MI; i++)
        #pragma unroll
        for (int j = 0; j < NI; j++)
            wmma::fill_fragment(acc[i][j], 0.0f);

    for (int k0 = 0; k0 < K; k0 += BK) {
        {
            constexpr int SLOTS = BM * (BK / 4);
            #pragma unroll
            for (int p = 0; p < SLOTS / 256; ++p) {
                int i = tid + p * 256;
                int m = i / (BK / 4);
                int q = i % (BK / 4);
                float4 f4 = *(const float4*)(A + (long long)(bm + m) * lda + k0 + q * 4);
                uint2 hi, lo;
                split4(f4, hi, lo);
                *(uint2*)(Ah + m * LDA_S + q * 4) = hi;
                *(uint2*)(Al + m * LDA_S + q * 4) = lo;
            }
        }
        {
            constexpr int SLOTS = BN * (BK / 8);
            #pragma unroll
            for (int p = 0; p < SLOTS / 256; ++p) {
                int i = tid + p * 256;
                int n = i / (BK / 8);
                int q = i % (BK / 8);
                *(uint4*)(Bh + n * LDA_S + q * 8) =
                    *(const uint4*)(Bhg + (long long)(bn + n) * ldb + k0 + q * 8);
                *(uint4*)(Bl + n * LDA_S + q * 8) =
                    *(const uint4*)(Blg + (long long)(bn + n) * ldb + k0 + q * 8);
            }
        }
        __syncthreads();

        #pragma unroll
        for (int kk = 0; kk < BK; kk += 16) {
            wmma::fragment<wmma::matrix_a, 16, 16, 16, __nv_bfloat16, wmma::row_major> ahi[MI], alo[MI];
            #pragma unroll
            for (int i = 0; i < MI; i++) {
                wmma::load_matrix_sync(ahi[i], Ah + (wm + i * 16) * LDA_S + kk, LDA_S);
                wmma::load_matrix_sync(alo[i], Al + (wm + i * 16) * LDA_S + kk, LDA_S);
            }
            #pragma unroll
            for (int j = 0; j < NI; j++) {
                wmma::fragment<wmma::matrix_b, 16, 16, 16, __nv_bfloat16, wmma::col_major> bhi, blo;
                wmma::load_matrix_sync(bhi, Bh + (wn + j * 16) * LDA_S + kk, LDA_S);
                wmma::load_matrix_sync(blo, Bl + (wn + j * 16) * LDA_S + kk, LDA_S);
                #pragma unroll
                for (int i = 0; i < MI; i++) {
                    wmma::mma_sync(acc[i][j], ahi[i], bhi, acc[i][j]);
                    wmma::mma_sync(acc[i][j], alo[i], bhi, acc[i][j]);
                    wmma::mma_sync(acc[i][j], ahi[i], blo, acc[i][j]);
                }
            }
        }
        __syncthreads();
    }

    constexpr int LDS_T = WN + 4;
    float* stg = (float*)smraw + (warp % MW) * (WM * LDS_T);
    #pragma unroll
    for (int wave = 0; wave < NW; ++wave) {
        if ((warp / MW) == wave) {
            #pragma unroll
            for (int i = 0; i < MI; i++)
                #pragma unroll
                for (int j = 0; j < NI; j++)
                    wmma::store_matrix_sync(&stg[(i * 16) * LDS_T + j * 16], acc[i][j],
                                            LDS_T, wmma::mem_row_major);
            __syncwarp();
            for (int idx = lane; idx < WM * WN; idx += 32) {
                int r  = idx / WN, c2 = idx % WN;
                int gr = bm + wm + r, gc = bn + wn + c2;
                float vv = stg[r * LDS_T + c2];
                if (bias) vv += bias[gc];
                if constexpr (EPI == 1) vv = gelu_f(vv);
                if constexpr (EPI == 2) vv += res[(long long)gr * ldc + gc];
                C[(long long)gr * ldc + gc] = vv;
            }
        }
        __syncthreads();
    }
}

// =============================================================================
// Fused causal flash attention (FA2-style), bf16 3-term split, raw mma PTX.
// Q,K,V,O: [B*T, D] fp32, head h occupies cols [h*64, h*64+64).
// Grid: (T/128, B*H). 256 threads = 8 warps, each owns a 16-row Q band.
// smem (73728 B): Qh|Ql [128][72], Kh|Kl [64][72], Vth|Vtl [64][72] (V transposed)
// =============================================================================
#define FA_LD 72
#define FA_SMEM 73728

__global__ __launch_bounds__(256, 2)
void fa_kernel(const float* __restrict__ Qg, const float* __restrict__ Kg,
               const float* __restrict__ Vg, float* __restrict__ Og)
{
    const int bq = blockIdx.x, bh = blockIdx.y;
    const int b = bh / H_, hh = bh % H_;
    const int q0 = bq * 128;
    const int tid = threadIdx.x, warp = tid >> 5, lane = tid & 31;

    extern __shared__ __align__(16) char smraw[];
    __nv_bfloat16* Qh  = (__nv_bfloat16*)(smraw);
    __nv_bfloat16* Ql  = (__nv_bfloat16*)(smraw + 18432);
    __nv_bfloat16* Kh  = (__nv_bfloat16*)(smraw + 36864);
    __nv_bfloat16* Kl  = (__nv_bfloat16*)(smraw + 46080);
    __nv_bfloat16* Vth = (__nv_bfloat16*)(smraw + 55296);
    __nv_bfloat16* Vtl = (__nv_bfloat16*)(smraw + 64512);

    const float* Qb = Qg + ((long long)(b * T_ + q0)) * D_ + hh * DH_;
    const float* Kb = Kg + ((long long)b * T_) * D_ + hh * DH_;
    const float* Vb = Vg + ((long long)b * T_) * D_ + hh * DH_;

    // ---- stage Q (pre-scaled by 1/sqrt(64)=0.125), split hi/lo ----
    #pragma unroll
    for (int p = 0; p < 8; ++p) {
        int sidx = tid + p * 256;
        int r = sidx >> 4, c4 = (sidx & 15) << 2;
        float4 f4 = *(const float4*)(Qb + (long long)r * D_ + c4);
        f4.x *= 0.125f; f4.y *= 0.125f; f4.z *= 0.125f; f4.w *= 0.125f;
        uint2 hi, lo;
        split4(f4, hi, lo);
        *(uint2*)(Qh + r * FA_LD + c4) = hi;
        *(uint2*)(Ql + r * FA_LD + c4) = lo;
    }

    const int rA  = 16 * warp + (lane >> 2);   // local row (rB = rA + 8)
    const int grA = q0 + rA;                   // global row for causal mask

    float mA = -1e30f, mB = -1e30f, lA = 0.f, lB = 0.f;
    float oacc[32];
    #pragma unroll
    for (int i = 0; i < 32; i++) oacc[i] = 0.f;

    const int ntiles = (q0 + 128) / 64;        // 2*bq + 2

    for (int t = 0; t < ntiles; ++t) {
        const int kv0 = t * 64;
        __syncthreads();   // previous iteration's reads done before restage

        // ---- stage K tile [64][64] -> Kh/Kl [kv][dh] ----
        #pragma unroll
        for (int p = 0; p < 4; ++p) {
            int sidx = tid + p * 256;
            int r = sidx >> 4, c4 = (sidx & 15) << 2;
            float4 f4 = *(const float4*)(Kb + (long long)(kv0 + r) * D_ + c4);
            uint2 hi, lo;
            split4(f4, hi, lo);
            *(uint2*)(Kh + r * FA_LD + c4) = hi;
            *(uint2*)(Kl + r * FA_LD + c4) = lo;
        }
        // ---- stage V tile transposed -> Vth/Vtl [dh][kv] ----
        #pragma unroll
        for (int p = 0; p < 4; ++p) {
            int sidx = tid + p * 256;
            int r = sidx >> 4, c4 = (sidx & 15) << 2;
            float4 f4 = *(const float4*)(Vb + (long long)(kv0 + r) * D_ + c4);
            float vv[4] = {f4.x, f4.y, f4.z, f4.w};
            #pragma unroll
            for (int i = 0; i < 4; ++i) {
                __nv_bfloat16 hb = __float2bfloat16(vv[i]);
                Vth[(c4 + i) * FA_LD + r] = hb;
                Vtl[(c4 + i) * FA_LD + r] = __float2bfloat16(vv[i] - __bfloat162float(hb));
            }
        }
        __syncthreads();

        // ---- S = Q K^T (16 x 64 per warp), 3-term split ----
        float sacc[32];
        #pragma unroll
        for (int i = 0; i < 32; i++) sacc[i] = 0.f;
        #pragma unroll
        for (int ks = 0; ks < 4; ++ks) {
            const int k0 = ks * 16 + (lane & 3) * 2;
            uint32_t ah[4], al[4];
            ah[0] = *(const uint32_t*)(Qh + rA * FA_LD + k0);
            ah[1] = *(const uint32_t*)(Qh + (rA + 8) * FA_LD + k0);
            ah[2] = *(const uint32_t*)(Qh + rA * FA_LD + k0 + 8);
            ah[3] = *(const uint32_t*)(Qh + (rA + 8) * FA_LD + k0 + 8);
            al[0] = *(const uint32_t*)(Ql + rA * FA_LD + k0);
            al[1] = *(const uint32_t*)(Ql + (rA + 8) * FA_LD + k0);
            al[2] = *(const uint32_t*)(Ql + rA * FA_LD + k0 + 8);
            al[3] = *(const uint32_t*)(Ql + (rA + 8) * FA_LD + k0 + 8);
            #pragma unroll
            for (int nt = 0; nt < 8; ++nt) {
                const int n = nt * 8 + (lane >> 2);
                uint32_t bh0 = *(const uint32_t*)(Kh + n * FA_LD + k0);
                uint32_t bh1 = *(const uint32_t*)(Kh + n * FA_LD + k0 + 8);
                uint32_t bl0 = *(const uint32_t*)(Kl + n * FA_LD + k0);
                uint32_t bl1 = *(const uint32_t*)(Kl + n * FA_LD + k0 + 8);
                mma16816(sacc + 4 * nt, ah, bh0, bh1);
                mma16816(sacc + 4 * nt, al, bh0, bh1);
                mma16816(sacc + 4 * nt, ah, bl0, bl1);
            }
        }

        // ---- causal mask (diagonal tiles only) ----
        if (kv0 + 63 > grA) {
            #pragma unroll
            for (int nt = 0; nt < 8; ++nt) {
                const int c = kv0 + nt * 8 + (lane & 3) * 2;
                if (c     > grA)     sacc[4 * nt + 0] = -1e30f;
                if (c + 1 > grA)     sacc[4 * nt + 1] = -1e30f;
                if (c     > grA + 8) sacc[4 * nt + 2] = -1e30f;
                if (c + 1 > grA + 8) sacc[4 * nt + 3] = -1e30f;
            }
        }

        // ---- online softmax ----
        float mxA = -1e30f, mxB = -1e30f;
        #pragma unroll
        for (int nt = 0; nt < 8; ++nt) {
            mxA = fmaxf(mxA, fmaxf(sacc[4 * nt + 0], sacc[4 * nt + 1]));
            mxB = fmaxf(mxB, fmaxf(sacc[4 * nt + 2], sacc[4 * nt + 3]));
        }
        mxA = fmaxf(mxA, __shfl_xor_sync(0xffffffffu, mxA, 1));
        mxA = fmaxf(mxA, __shfl_xor_sync(0xffffffffu, mxA, 2));
        mxB = fmaxf(mxB, __shfl_xor_sync(0xffffffffu, mxB, 1));
        mxB = fmaxf(mxB, __shfl_xor_sync(0xffffffffu, mxB, 2));
        const float mAn = fmaxf(mA, mxA), mBn = fmaxf(mB, mxB);
        const float alA = exp2f((mA - mAn) * 1.44269504f);
        const float alB = exp2f((mB - mBn) * 1.44269504f);
        mA = mAn; mB = mBn;

        float sumA = 0.f, sumB = 0.f;
        #pragma unroll
        for (int nt = 0; nt < 8; ++nt) {
            sacc[4 * nt + 0] = exp2f((sacc[4 * nt + 0] - mAn) * 1.44269504f);
            sacc[4 * nt + 1] = exp2f((sacc[4 * nt + 1] - mAn) * 1.44269504f);
            sacc[4 * nt + 2] = exp2f((sacc[4 * nt + 2] - mBn) * 1.44269504f);
            sacc[4 * nt + 3] = exp2f((sacc[4 * nt + 3] - mBn) * 1.44269504f);
            sumA += sacc[4 * nt + 0] + sacc[4 * nt + 1];
            sumB += sacc[4 * nt + 2] + sacc[4 * nt + 3];
        }
        sumA += __shfl_xor_sync(0xffffffffu, sumA, 1);
        sumA += __shfl_xor_sync(0xffffffffu, sumA, 2);
        sumB += __shfl_xor_sync(0xffffffffu, sumB, 1);
        sumB += __shfl_xor_sync(0xffffffffu, sumB, 2);
        lA = lA * alA + sumA;
        lB = lB * alB + sumB;
        #pragma unroll
        for (int nt = 0; nt < 8; ++nt) {
            oacc[4 * nt + 0] *= alA;
            oacc[4 * nt + 1] *= alA;
            oacc[4 * nt + 2] *= alB;
            oacc[4 * nt + 3] *= alB;
        }

        // ---- O += P V, P packed from sacc regs (C-layout == A-layout) ----
        #pragma unroll
        for (int ks = 0; ks < 4; ++ks) {
            const int u = 2 * ks, v2 = 2 * ks + 1;
            uint32_t pah[4], pal[4];
            pack_split2(sacc[4 * u + 0],  sacc[4 * u + 1],  pah[0], pal[0]);
            pack_split2(sacc[4 * u + 2],  sacc[4 * u + 3],  pah[1], pal[1]);
            pack_split2(sacc[4 * v2 + 0], sacc[4 * v2 + 1], pah[2], pal[2]);
            pack_split2(sacc[4 * v2 + 2], sacc[4 * v2 + 3], pah[3], pal[3]);
            const int k0 = ks * 16 + (lane & 3) * 2;
            #pragma unroll
            for (int nt = 0; nt < 8; ++nt) {
                const int n = nt * 8 + (lane >> 2);
                uint32_t bh0 = *(const uint32_t*)(Vth + n * FA_LD + k0);
                uint32_t bh1 = *(const uint32_t*)(Vth + n * FA_LD + k0 + 8);
                uint32_t bl0 = *(const uint32_t*)(Vtl + n * FA_LD + k0);
                uint32_t bl1 = *(const uint32_t*)(Vtl + n * FA_LD + k0 + 8);
                mma16816(oacc + 4 * nt, pah, bh0, bh1);
                mma16816(oacc + 4 * nt, pal, bh0, bh1);
                mma16816(oacc + 4 * nt, pah, bl0, bl1);
            }
        }
    }

    // ---- epilogue: O /= l, write fp32 ----
    const float ilA = 1.0f / lA, ilB = 1.0f / lB;
    float* Ob = Og + ((long long)(b * T_ + q0)) * D_ + hh * DH_;
    #pragma unroll
    for (int nt = 0; nt < 8; ++nt) {
        const int c = nt * 8 + (lane & 3) * 2;
        float2 r0 = make_float2(oacc[4 * nt + 0] * ilA, oacc[4 * nt + 1] * ilA);
        float2 r1 = make_float2(oacc[4 * nt + 2] * ilB, oacc[4 * nt + 3] * ilB);
        *(float2*)(Ob + (long long)rA * D_ + c)       = r0;
        *(float2*)(Ob + (long long)(rA + 8) * D_ + c) = r1;
    }
}

// ---------------- LayerNorm ----------------------------------------------------
__global__ __launch_bounds__(256)
void ln_kernel(const float* __restrict__ x, const float* __restrict__ g,
               const float* __restrict__ b, float* __restrict__ o)
{
    __shared__ float shs[8], shs2[8], shbc[2];
    const int row = blockIdx.x;
    const float* xr = x + (long long)row * D_;
    float* orow     = o + (long long)row * D_;
    const int t = threadIdx.x;
    float v[4]; float s = 0.f, s2 = 0.f;
    #pragma unroll
    for (int i = 0; i < 4; i++) { v[i] = xr[t + i * 256]; s += v[i]; s2 += v[i] * v[i]; }
    #pragma unroll
    for (int off = 16; off; off >>= 1) {
        s  += __shfl_xor_sync(0xffffffffu, s,  off);
        s2 += __shfl_xor_sync(0xffffffffu, s2, off);
    }
    if ((t & 31) == 0) { shs[t >> 5] = s; shs2[t >> 5] = s2; }
    __syncthreads();
    if (t < 32) {
        s  = (t < 8) ? shs[t]  : 0.f;
        s2 = (t < 8) ? shs2[t] : 0.f;
        #pragma unroll
        for (int off = 4; off; off >>= 1) {
            s  += __shfl_xor_sync(0xffffffffu, s,  off);
            s2 += __shfl_xor_sync(0xffffffffu, s2, off);
        }
        if (t == 0) {
            float mu = s * (1.0f / D_);
            shbc[0] = mu;
            shbc[1] = rsqrtf(s2 * (1.0f / D_) - mu * mu + 1e-5f);
        }
    }
    __syncthreads();
    const float mu = shbc[0], inv = shbc[1];
    #pragma unroll
    for (int i = 0; i < 4; i++) {
        int c = t + i * 256;
        orow[c] = (v[i] - mu) * inv * g[c] + b[c];
    }
}

// ---------------- embedding ---------------------------------------------------
__global__ __launch_bounds__(256)
void embed_kernel(const int* __restrict__ idx, const float* __restrict__ tok,
                  const float* __restrict__ pos, float* __restrict__ x)
{
    const int bt = blockIdx.x;
    const int tk = idx[bt];
    const int tt = bt % T_;
    const float* tr = tok + (long long)tk * D_;
    const float* pr = pos + (long long)tt * D_;
    float* xr = x + (long long)bt * D_;
    for (int i = threadIdx.x; i < D_; i += 256) xr[i] = tr[i] + pr[i];
}

// ---------------- host wrappers -----------------------------------------------
#define GEMM_SMEM 73728

template<int BM, int BN, int BK, int WM, int WN, int EPI>
static void gemm(const float* A, const __nv_bfloat16* B0, const __nv_bfloat16* B1,
                 const float* bias, const float* res, float* C,
                 int M, int N, int K, int lda, int ldb, int ldc)
{
    static bool init = false;
    if (!init) {
        cudaFuncSetAttribute(gemm_bf<BM, BN, BK, WM, WN, EPI>,
                             cudaFuncAttributeMaxDynamicSharedMemorySize, GEMM_SMEM);
        init = true;
    }
    dim3 grid(N / BN, M / BM, 1);
    gemm_bf<BM, BN, BK, WM, WN, EPI><<<grid, 256, GEMM_SMEM>>>(
        A, B0, B1, bias, res, C, M, N, K, lda, ldb, ldc);
}

extern "C" void kernel_launch(void* const* d_in, const int* in_sizes, int n_in,
                              void* d_out, int out_size)
{
    (void)in_sizes; (void)n_in; (void)out_size;
    const int*   idx   = (const int*)  d_in[0];
    const float* tok   = (const float*)d_in[1];
    const float* pos   = (const float*)d_in[2];
    const float* ln1g  = (const float*)d_in[3];
    const float* ln1b  = (const float*)d_in[4];
    const float* Wq    = (const float*)d_in[5];
    const float* bq    = (const float*)d_in[6];
    const float* Wk    = (const float*)d_in[7];
    const float* bk    = (const float*)d_in[8];
    const float* Wv    = (const float*)d_in[9];
    const float* bv    = (const float*)d_in[10];
    const float* Wo    = (const float*)d_in[11];
    const float* bo    = (const float*)d_in[12];
    const float* ln2g  = (const float*)d_in[13];
    const float* ln2b  = (const float*)d_in[14];
    const float* W1    = (const float*)d_in[15];
    const float* b1    = (const float*)d_in[16];
    const float* W2    = (const float*)d_in[17];
    const float* b2    = (const float*)d_in[18];
    const float* lnfg  = (const float*)d_in[19];
    const float* lnfb  = (const float*)d_in[20];
    const float* Wh    = (const float*)d_in[21];
    const float* bh    = (const float*)d_in[22];

    float *x, *h, *q, *k, *v, *o, *ff;
    __nv_bfloat16 *whi, *wlo;
    cudaGetSymbolAddress((void**)&x,   g_x);
    cudaGetSymbolAddress((void**)&h,   g_h);
    cudaGetSymbolAddress((void**)&q,   g_q);
    cudaGetSymbolAddress((void**)&k,   g_k);
    cudaGetSymbolAddress((void**)&v,   g_v);
    cudaGetSymbolAddress((void**)&o,   g_o);
    cudaGetSymbolAddress((void**)&ff,  g_ff);
    cudaGetSymbolAddress((void**)&whi, g_whi);
    cudaGetSymbolAddress((void**)&wlo, g_wlo);

    cudaFuncSetAttribute(fa_kernel, cudaFuncAttributeMaxDynamicSharedMemorySize, FA_SMEM);

    // -------- weight transpose + split (captured in graph; runs every replay) --
    const size_t WD = (size_t)D_ * D_;
    const size_t LW = 4 * WD + (size_t)D_ * FF_ + (size_t)FF_ * D_;
    for (int l = 0; l < L_; ++l) {
        size_t base = (size_t)l * LW;
        wsplit_kernel<<<dim3(D_ / 32, D_ / 32), 256>>>(Wq + (size_t)l * WD, whi + base,          wlo + base,          D_, D_);
        wsplit_kernel<<<dim3(D_ / 32, D_ / 32), 256>>>(Wk + (size_t)l * WD, whi + base + WD,     wlo + base + WD,     D_, D_);
        wsplit_kernel<<<dim3(D_ / 32, D_ / 32), 256>>>(Wv + (size_t)l * WD, whi + base + 2 * WD, wlo + base + 2 * WD, D_, D_);
        wsplit_kernel<<<dim3(D_ / 32, D_ / 32), 256>>>(Wo + (size_t)l * WD, whi + base + 3 * WD, wlo + base + 3 * WD, D_, D_);
        wsplit_kernel<<<dim3(FF_ / 32, D_ / 32), 256>>>(W1 + (size_t)l * D_ * FF_, whi + base + 4 * WD,                    wlo + base + 4 * WD,                    D_, FF_);
        wsplit_kernel<<<dim3(D_ / 32, FF_ / 32), 256>>>(W2 + (size_t)l * FF_ * D_, whi + base + 4 * WD + (size_t)D_ * FF_, wlo + base + 4 * WD + (size_t)D_ * FF_, FF_, D_);
    }
    const size_t off_wh = 8 * LW;
    wsplit_kernel<<<dim3(V_ / 32, D_ / 32), 256>>>(Wh, whi + off_wh, wlo + off_wh, D_, V_);

    embed_kernel<<<M_, 256>>>(idx, tok, pos, x);

    for (int l = 0; l < L_; ++l) {
        size_t base = (size_t)l * LW;
        const __nv_bfloat16 *qh = whi + base,          *ql = wlo + base;
        const __nv_bfloat16 *kh = whi + base + WD,     *kl = wlo + base + WD;
        const __nv_bfloat16 *vh = whi + base + 2 * WD, *vl = wlo + base + 2 * WD;
        const __nv_bfloat16 *oh = whi + base + 3 * WD, *ol = wlo + base + 3 * WD;
        const __nv_bfloat16 *w1h = whi + base + 4 * WD,                    *w1l = wlo + base + 4 * WD;
        const __nv_bfloat16 *w2h = whi + base + 4 * WD + (size_t)D_ * FF_, *w2l = wlo + base + 4 * WD + (size_t)D_ * FF_;

        // ln1 -> h
        ln_kernel<<<M_, 256>>>(x, ln1g + (size_t)l * D_, ln1b + (size_t)l * D_, h);

        // q, k, v projections
        gemm<128,128,64,32,64,0>(h, qh, ql, bq + (size_t)l * D_, nullptr, q, M_, D_, D_, D_, D_, D_);
        gemm<128,128,64,32,64,0>(h, kh, kl, bk + (size_t)l * D_, nullptr, k, M_, D_, D_, D_, D_, D_);
        gemm<128,128,64,32,64,0>(h, vh, vl, bv + (size_t)l * D_, nullptr, v, M_, D_, D_, D_, D_, D_);

        // fused causal attention: o = softmax(q k^T / 8) v
        fa_kernel<<<dim3(T_ / 128, B_ * H_), 256, FA_SMEM>>>(q, k, v, o);

        // x = x + O @ Wo + bo
        gemm<128,128,64,32,64,2>(o, oh, ol, bo + (size_t)l * D_, x, x, M_, D_, D_, D_, D_, D_);

        // ln2 -> h
        ln_kernel<<<M_, 256>>>(x, ln2g + (size_t)l * D_, ln2b + (size_t)l * D_, h);

        // ff = gelu(h @ W1 + b1)
        gemm<128,128,64,32,64,1>(h, w1h, w1l, b1 + (size_t)l * FF_, nullptr, ff, M_, FF_, D_, D_, D_, FF_);

        // x = x + ff @ W2 + b2
        gemm<128,128,64,32,64,2>(ff, w2h, w2l, b2 + (size_t)l * D_, x, x, M_, D_, FF_, FF_, FF_, D_);
    }

    // final LN + head
    ln_kernel<<<M_, 256>>>(x, lnfg, lnfb, h);
    gemm<128,128,64,32,64,0>(h, whi + off_wh, wlo + off_wh, bh, nullptr, (float*)d_out, M_, V_, D_, D_, D_, V_);
}